// round 12
// baseline (speedup 1.0000x reference)
#include <cuda_runtime.h>
#include <cuda_bf16.h>
#include <cuda_fp16.h>
#include <cstdint>

#define G_NUM 1024
#define D 128

// ---------------------------------------------------------------------------
// Device scratch
// ---------------------------------------------------------------------------
__device__ int   g_segstart[G_NUM + 1];
__device__ float g_sums[G_NUM * D];
__device__ float g_C[G_NUM * D];
__device__ float g_W2t[D * D];                 // W2 transposed: [k][t]
__device__ __align__(16) uint32_t g_Bf[8192];  // W1 fp16 B-fragments (col-permuted)

// ---------------------------------------------------------------------------
// Helpers
// ---------------------------------------------------------------------------
__device__ __forceinline__ uint32_t smem_u32(const void* p) {
    return (uint32_t)__cvta_generic_to_shared((void*)p);
}
__device__ __forceinline__ uint32_t pack_f16(float lo, float hi) {
    uint32_t r;
    asm("cvt.rn.f16x2.f32 %0, %1, %2;" : "=r"(r) : "f"(hi), "f"(lo));
    return r;
}
__device__ __forceinline__ float lo_h(uint32_t p) {
    return __half2float(__ushort_as_half((unsigned short)(p & 0xffff)));
}
__device__ __forceinline__ float hi_h(uint32_t p) {
    return __half2float(__ushort_as_half((unsigned short)(p >> 16)));
}
__device__ __forceinline__ void mma_f16(float* d, const uint32_t* a, const uint32_t* b) {
    asm volatile(
        "mma.sync.aligned.m16n8k16.row.col.f32.f16.f16.f32 "
        "{%0,%1,%2,%3}, {%4,%5,%6,%7}, {%8,%9}, {%0,%1,%2,%3};"
        : "+f"(d[0]), "+f"(d[1]), "+f"(d[2]), "+f"(d[3])
        : "r"(a[0]), "r"(a[1]), "r"(a[2]), "r"(a[3]), "r"(b[0]), "r"(b[1]));
}
__device__ __forceinline__ void cp16(uint32_t dst, const void* src) {
    asm volatile("cp.async.cg.shared.global [%0], [%1], 16;"
                 :: "r"(dst), "l"(src) : "memory");
}
#define CP_COMMIT() asm volatile("cp.async.commit_group;" ::: "memory")
#define CP_WAIT(n)  asm volatile("cp.async.wait_group %0;" :: "n"(n) : "memory")

// ---------------------------------------------------------------------------
// K1: zero sums + segment boundaries + W1 B-fragments + W2 transpose
// ---------------------------------------------------------------------------
__global__ void k_prep(const int* __restrict__ bid, int N, const float* __restrict__ W) {
    int i = blockIdx.x * blockDim.x + threadIdx.x;
    if (i < G_NUM * D) g_sums[i] = 0.f;
    if (i < N) {
        int b = bid[i];
        int prev = (i == 0) ? -1 : bid[i - 1];
        for (int g = prev + 1; g <= b; ++g) g_segstart[g] = i;
        if (i == N - 1)
            for (int g = b + 1; g <= G_NUM; ++g) g_segstart[g] = N;
    }
    if (i < 4096) {
        int ks = i >> 9;
        int na = (i >> 5) & 15;
        int l  = i & 31;
        int c  = l & 3;
        int n  = na * 8 + (l >> 2);
        int k0 = ks * 16 + 4 * c;
        const float* wr = W + (size_t)n * 256;
        g_Bf[i * 2 + 0] = pack_f16(wr[k0],     wr[k0 + 1]);
        g_Bf[i * 2 + 1] = pack_f16(wr[k0 + 2], wr[k0 + 3]);
    }
    if (i < D * D) {
        int k = i >> 7, t = i & 127;
        g_W2t[i] = W[(size_t)t * 256 + 128 + k];
    }
}

// ---------------------------------------------------------------------------
// K2: segment sums via cp.async double-buffered smem pipeline (R11 config)
// ---------------------------------------------------------------------------
__global__ void __launch_bounds__(256)
k_sum(const float* __restrict__ x, const int* __restrict__ bid, int N) {
    __shared__ __align__(16) float buf[2][32 * 128];
    __shared__ int sb[256];
    int tid = threadIdx.x;
    int n0 = blockIdx.x * 256;
    sb[tid] = (n0 + tid < N) ? bid[n0 + tid] : -1;
    __syncthreads();

    int h = tid >> 5;
    int q = tid & 31;
    const float4 z4 = make_float4(0.f, 0.f, 0.f, 0.f);
    float4 acc = z4;
    int curbid = sb[h];

    if (n0 + 256 > N) {
#pragma unroll 4
        for (int r = h; r < 256; r += 8) {
            int bv = sb[r];
            if (bv != curbid) {
                if (curbid >= 0) {
                    float* dst = &g_sums[curbid * D + q * 4];
                    atomicAdd(dst + 0, acc.x); atomicAdd(dst + 1, acc.y);
                    atomicAdd(dst + 2, acc.z); atomicAdd(dst + 3, acc.w);
                }
                acc = z4; curbid = bv;
            }
            if (bv >= 0) {
                float4 v = *(const float4*)(x + (size_t)(n0 + r) * D + q * 4);
                acc.x += v.x; acc.y += v.y; acc.z += v.z; acc.w += v.w;
            }
        }
        if (curbid >= 0) {
            float* dst = &g_sums[curbid * D + q * 4];
            atomicAdd(dst + 0, acc.x); atomicAdd(dst + 1, acc.y);
            atomicAdd(dst + 2, acc.z); atomicAdd(dst + 3, acc.w);
        }
        return;
    }

    const float4* src = (const float4*)(x + (size_t)n0 * 128);
    uint32_t sb0 = smem_u32(&buf[0][0]);
    uint32_t sb1 = smem_u32(&buf[1][0]);

#define STAGE(c, s)                                                            \
    do {                                                                       \
        uint32_t _d = ((s) ? sb1 : sb0) + (uint32_t)tid * 16;                  \
        const float4* _p = src + (c) * 1024 + tid;                             \
        cp16(_d + 0 * 4096, _p + 0 * 256);                                     \
        cp16(_d + 1 * 4096, _p + 1 * 256);                                     \
        cp16(_d + 2 * 4096, _p + 2 * 256);                                     \
        cp16(_d + 3 * 4096, _p + 3 * 256);                                     \
        CP_COMMIT();                                                           \
    } while (0)

    STAGE(0, 0);
#pragma unroll
    for (int c = 0; c < 8; ++c) {
        if (c < 7) {
            STAGE(c + 1, (c + 1) & 1);
            CP_WAIT(1);
        } else {
            CP_WAIT(0);
        }
        __syncthreads();
        const float* bp = buf[c & 1];
#pragma unroll
        for (int rr = 0; rr < 4; ++rr) {
            int r = rr * 8 + h;
            int bv = sb[c * 32 + r];
            float4 v = *(const float4*)(bp + r * 128 + q * 4);
            if (bv != curbid) {
                if (curbid >= 0) {
                    float* dst = &g_sums[curbid * D + q * 4];
                    atomicAdd(dst + 0, acc.x); atomicAdd(dst + 1, acc.y);
                    atomicAdd(dst + 2, acc.z); atomicAdd(dst + 3, acc.w);
                }
                acc = z4; curbid = bv;
            }
            acc.x += v.x; acc.y += v.y; acc.z += v.z; acc.w += v.w;
        }
        __syncthreads();
    }
#undef STAGE

    if (curbid >= 0) {
        float* dst = &g_sums[curbid * D + q * 4];
        atomicAdd(dst + 0, acc.x); atomicAdd(dst + 1, acc.y);
        atomicAdd(dst + 2, acc.z); atomicAdd(dst + 3, acc.w);
    }
}

// ---------------------------------------------------------------------------
// K3: C[g] = (sums[g]/cnt) @ W2^T + b
// ---------------------------------------------------------------------------
__global__ void k_ctx(const float* __restrict__ b) {
    __shared__ float sm[D];
    int g = blockIdx.x, t = threadIdx.x;
    int s = g_segstart[g], e = g_segstart[g + 1];
    int cnt = e - s;
    float inv = 1.f / (float)(cnt > 0 ? cnt : 1);
    sm[t] = g_sums[g * D + t] * inv;
    __syncthreads();
    float c = b[t];
#pragma unroll 8
    for (int k = 0; k < D; ++k) c += sm[k] * g_W2t[k * 128 + t];
    g_C[g * D + t] = c;
}

// ---------------------------------------------------------------------------
// K4: fp16x2 mma.sync GEMM. CTA 128x128, 8 warps: warp = 32 rows x 64 cols
// (4 row-groups x 2 col-groups). Each B fragment feeds 4 MMAs -> B-LDS
// bytes per output halved vs 16-row warps. 2 CTA/SM.
// ---------------------------------------------------------------------------
#define STG_STRIDE 136
#define SMEM_BYTES (128 * STG_STRIDE * 4)

__global__ void __launch_bounds__(256, 2)
k_gemm(const float* __restrict__ x, const int* __restrict__ bid,
       float* __restrict__ out, int N) {
    extern __shared__ __align__(16) uint32_t sh[];
    uint32_t* shB = sh;

    int tid = threadIdx.x;
    int w   = tid >> 5;
    int l   = tid & 31;
    int n0  = blockIdx.x * 128;

#pragma unroll
    for (int i = 0; i < 8; ++i) {
        int q = i * 256 + tid;
        *(uint4*)(shB + q * 4) = *(const uint4*)(g_Bf + q * 4);
    }
    __syncthreads();

    int g4 = l >> 2, c4 = l & 3;
    int wm = w & 3;            // row group: rows wm*32 .. wm*32+31
    int wn = w >> 2;           // col group: cols wn*64 .. wn*64+63

    int rb = n0 + wm * 32;
    const float* p0 = x + (size_t)(rb + g4) * 128;       // m-atom0 row a
    const float* p1 = x + (size_t)(rb + 8 + g4) * 128;   // m-atom0 row b
    const float* p2 = x + (size_t)(rb + 16 + g4) * 128;  // m-atom1 row a
    const float* p3 = x + (size_t)(rb + 24 + g4) * 128;  // m-atom1 row b
    bool full = (n0 + 128) <= N;
    bool v0 = full || (rb + g4) < N;
    bool v1 = full || (rb + 8 + g4) < N;
    bool v2 = full || (rb + 16 + g4) < N;
    bool v3 = full || (rb + 24 + g4) < N;
    const float4 z4 = make_float4(0.f, 0.f, 0.f, 0.f);

    float acc[2][8][4];
#pragma unroll
    for (int mt = 0; mt < 2; ++mt)
#pragma unroll
        for (int na = 0; na < 8; ++na)
#pragma unroll
            for (int j = 0; j < 4; ++j) acc[mt][na][j] = 0.f;

    float4 cur[4], nxt[4];

#define LOAD_KS(dst, ks)                                                       \
    do {                                                                       \
        int k0_ = (ks) * 16 + 4 * c4;                                          \
        dst[0] = v0 ? *(const float4*)(p0 + k0_) : z4;                         \
        dst[1] = v1 ? *(const float4*)(p1 + k0_) : z4;                         \
        dst[2] = v2 ? *(const float4*)(p2 + k0_) : z4;                         \
        dst[3] = v3 ? *(const float4*)(p3 + k0_) : z4;                         \
    } while (0)

    LOAD_KS(cur, 0);

#pragma unroll
    for (int ks = 0; ks < 8; ++ks) {
        if (ks < 7) LOAD_KS(nxt, ks + 1);

        uint32_t ahi[2][4], alo[2][4];
#pragma unroll
        for (int mt = 0; mt < 2; ++mt) {
            float4 u = cur[2 * mt + 0];
            float4 v = cur[2 * mt + 1];
            ahi[mt][0] = pack_f16(u.x, u.y);
            ahi[mt][1] = pack_f16(v.x, v.y);
            ahi[mt][2] = pack_f16(u.z, u.w);
            ahi[mt][3] = pack_f16(v.z, v.w);
            alo[mt][0] = pack_f16(u.x - lo_h(ahi[mt][0]), u.y - hi_h(ahi[mt][0]));
            alo[mt][1] = pack_f16(v.x - lo_h(ahi[mt][1]), v.y - hi_h(ahi[mt][1]));
            alo[mt][2] = pack_f16(u.z - lo_h(ahi[mt][2]), u.w - hi_h(ahi[mt][2]));
            alo[mt][3] = pack_f16(v.z - lo_h(ahi[mt][3]), v.w - hi_h(ahi[mt][3]));
        }

        const uint32_t* bks = shB + (ks * 16 + wn * 8) * 64;
#pragma unroll
        for (int na = 0; na < 8; ++na) {
            uint2 bh = *(const uint2*)(bks + na * 64 + l * 2);
            uint32_t bhr[2] = {bh.x, bh.y};
            mma_f16(acc[0][na], ahi[0], bhr);
            mma_f16(acc[0][na], alo[0], bhr);
            mma_f16(acc[1][na], ahi[1], bhr);
            mma_f16(acc[1][na], alo[1], bhr);
        }
#pragma unroll
        for (int j = 0; j < 4; ++j) cur[j] = nxt[j];
    }
#undef LOAD_KS

    // --- Epilogue: stage through smem, add C, store coalesced ---
    float* stg = (float*)sh;
    __syncthreads();
    {
#pragma unroll
        for (int mt = 0; mt < 2; ++mt) {
            int rl0 = wm * 32 + mt * 16 + g4;
#pragma unroll
            for (int na = 0; na < 8; ++na) {
                int cb = wn * 64 + na * 8 + 2 * c4;
                *(float2*)(stg + rl0 * STG_STRIDE + cb) =
                    make_float2(acc[mt][na][0], acc[mt][na][1]);
                *(float2*)(stg + (rl0 + 8) * STG_STRIDE + cb) =
                    make_float2(acc[mt][na][2], acc[mt][na][3]);
            }
        }
    }
    __syncthreads();
    {
        int cw = l * 4;
#pragma unroll
        for (int it = 0; it < 16; ++it) {
            int rloc = it * 8 + w;
            int n = n0 + rloc;
            if (n < N) {
                float4 v = *(float4*)(stg + rloc * STG_STRIDE + cw);
                int gidx = bid[n];
                float4 cv = *(const float4*)(g_C + (size_t)gidx * 128 + cw);
                v.x += cv.x; v.y += cv.y; v.z += cv.z; v.w += cv.w;
                *(float4*)(out + (size_t)n * 128 + cw) = v;
            }
        }
    }
}

// ---------------------------------------------------------------------------
extern "C" void kernel_launch(void* const* d_in, const int* in_sizes, int n_in,
                              void* d_out, int out_size) {
    const float* x   = (const float*)d_in[0];
    const int*   bid = (const int*)  d_in[1];
    const float* W   = (const float*)d_in[2];
    const float* b   = (const float*)d_in[3];
    float* out = (float*)d_out;
    int N = in_sizes[1];

    cudaFuncSetAttribute(k_gemm, cudaFuncAttributeMaxDynamicSharedMemorySize, SMEM_BYTES);

    k_prep<<<(N + 255) / 256, 256>>>(bid, N, W);
    k_sum<<<(N + 255) / 256, 256>>>(x, bid, N);
    k_ctx<<<G_NUM, 128>>>(b);
    k_gemm<<<(N + 127) / 128, 256, SMEM_BYTES>>>(x, bid, out, N);
}

// round 13
// speedup vs baseline: 1.0801x; 1.0801x over previous
#include <cuda_runtime.h>
#include <cuda_bf16.h>
#include <cuda_fp16.h>
#include <cstdint>

#define G_NUM 1024
#define D 128

// ---------------------------------------------------------------------------
// Device scratch
// ---------------------------------------------------------------------------
__device__ int   g_segstart[G_NUM + 1];
__device__ float g_sums[G_NUM * D];
__device__ float g_C[G_NUM * D];
__device__ float g_W2t[D * D];                 // W2 transposed: [k][t]
__device__ __align__(16) uint32_t g_Bf[8192];  // W1 fp16 B-fragments (col-permuted)

// ---------------------------------------------------------------------------
// Helpers
// ---------------------------------------------------------------------------
__device__ __forceinline__ uint32_t smem_u32(const void* p) {
    return (uint32_t)__cvta_generic_to_shared((void*)p);
}
__device__ __forceinline__ uint32_t pack_f16(float lo, float hi) {
    uint32_t r;
    asm("cvt.rn.f16x2.f32 %0, %1, %2;" : "=r"(r) : "f"(hi), "f"(lo));
    return r;
}
__device__ __forceinline__ float lo_h(uint32_t p) {
    return __half2float(__ushort_as_half((unsigned short)(p & 0xffff)));
}
__device__ __forceinline__ float hi_h(uint32_t p) {
    return __half2float(__ushort_as_half((unsigned short)(p >> 16)));
}
__device__ __forceinline__ void mma_f16(float* d, const uint32_t* a, const uint32_t* b) {
    asm volatile(
        "mma.sync.aligned.m16n8k16.row.col.f32.f16.f16.f32 "
        "{%0,%1,%2,%3}, {%4,%5,%6,%7}, {%8,%9}, {%0,%1,%2,%3};"
        : "+f"(d[0]), "+f"(d[1]), "+f"(d[2]), "+f"(d[3])
        : "r"(a[0]), "r"(a[1]), "r"(a[2]), "r"(a[3]), "r"(b[0]), "r"(b[1]));
}
__device__ __forceinline__ void cp16(uint32_t dst, const void* src) {
    asm volatile("cp.async.cg.shared.global [%0], [%1], 16;"
                 :: "r"(dst), "l"(src) : "memory");
}
#define CP_COMMIT() asm volatile("cp.async.commit_group;" ::: "memory")
#define CP_WAIT(n)  asm volatile("cp.async.wait_group %0;" :: "n"(n) : "memory")

// ---------------------------------------------------------------------------
// K1: zero sums + segment boundaries + W1 B-fragments + W2 transpose
// ---------------------------------------------------------------------------
__global__ void k_prep(const int* __restrict__ bid, int N, const float* __restrict__ W) {
    int i = blockIdx.x * blockDim.x + threadIdx.x;
    if (i < G_NUM * D) g_sums[i] = 0.f;
    if (i < N) {
        int b = bid[i];
        int prev = (i == 0) ? -1 : bid[i - 1];
        for (int g = prev + 1; g <= b; ++g) g_segstart[g] = i;
        if (i == N - 1)
            for (int g = b + 1; g <= G_NUM; ++g) g_segstart[g] = N;
    }
    if (i < 4096) {
        int ks = i >> 9;
        int na = (i >> 5) & 15;
        int l  = i & 31;
        int c  = l & 3;
        int n  = na * 8 + (l >> 2);
        int k0 = ks * 16 + 4 * c;
        const float* wr = W + (size_t)n * 256;
        g_Bf[i * 2 + 0] = pack_f16(wr[k0],     wr[k0 + 1]);
        g_Bf[i * 2 + 1] = pack_f16(wr[k0 + 2], wr[k0 + 3]);
    }
    if (i < D * D) {
        int k = i >> 7, t = i & 127;
        g_W2t[i] = W[(size_t)t * 256 + 128 + k];
    }
}

// ---------------------------------------------------------------------------
// K2: segment sums via cp.async double-buffered smem pipeline (R11 config)
// ---------------------------------------------------------------------------
__global__ void __launch_bounds__(256)
k_sum(const float* __restrict__ x, const int* __restrict__ bid, int N) {
    __shared__ __align__(16) float buf[2][32 * 128];
    __shared__ int sb[256];
    int tid = threadIdx.x;
    int n0 = blockIdx.x * 256;
    sb[tid] = (n0 + tid < N) ? bid[n0 + tid] : -1;
    __syncthreads();

    int h = tid >> 5;
    int q = tid & 31;
    const float4 z4 = make_float4(0.f, 0.f, 0.f, 0.f);
    float4 acc = z4;
    int curbid = sb[h];

    if (n0 + 256 > N) {
#pragma unroll 4
        for (int r = h; r < 256; r += 8) {
            int bv = sb[r];
            if (bv != curbid) {
                if (curbid >= 0) {
                    float* dst = &g_sums[curbid * D + q * 4];
                    atomicAdd(dst + 0, acc.x); atomicAdd(dst + 1, acc.y);
                    atomicAdd(dst + 2, acc.z); atomicAdd(dst + 3, acc.w);
                }
                acc = z4; curbid = bv;
            }
            if (bv >= 0) {
                float4 v = *(const float4*)(x + (size_t)(n0 + r) * D + q * 4);
                acc.x += v.x; acc.y += v.y; acc.z += v.z; acc.w += v.w;
            }
        }
        if (curbid >= 0) {
            float* dst = &g_sums[curbid * D + q * 4];
            atomicAdd(dst + 0, acc.x); atomicAdd(dst + 1, acc.y);
            atomicAdd(dst + 2, acc.z); atomicAdd(dst + 3, acc.w);
        }
        return;
    }

    const float4* src = (const float4*)(x + (size_t)n0 * 128);
    uint32_t sb0 = smem_u32(&buf[0][0]);
    uint32_t sb1 = smem_u32(&buf[1][0]);

#define STAGE(c, s)                                                            \
    do {                                                                       \
        uint32_t _d = ((s) ? sb1 : sb0) + (uint32_t)tid * 16;                  \
        const float4* _p = src + (c) * 1024 + tid;                             \
        cp16(_d + 0 * 4096, _p + 0 * 256);                                     \
        cp16(_d + 1 * 4096, _p + 1 * 256);                                     \
        cp16(_d + 2 * 4096, _p + 2 * 256);                                     \
        cp16(_d + 3 * 4096, _p + 3 * 256);                                     \
        CP_COMMIT();                                                           \
    } while (0)

    STAGE(0, 0);
#pragma unroll
    for (int c = 0; c < 8; ++c) {
        if (c < 7) {
            STAGE(c + 1, (c + 1) & 1);
            CP_WAIT(1);
        } else {
            CP_WAIT(0);
        }
        __syncthreads();
        const float* bp = buf[c & 1];
#pragma unroll
        for (int rr = 0; rr < 4; ++rr) {
            int r = rr * 8 + h;
            int bv = sb[c * 32 + r];
            float4 v = *(const float4*)(bp + r * 128 + q * 4);
            if (bv != curbid) {
                if (curbid >= 0) {
                    float* dst = &g_sums[curbid * D + q * 4];
                    atomicAdd(dst + 0, acc.x); atomicAdd(dst + 1, acc.y);
                    atomicAdd(dst + 2, acc.z); atomicAdd(dst + 3, acc.w);
                }
                acc = z4; curbid = bv;
            }
            acc.x += v.x; acc.y += v.y; acc.z += v.z; acc.w += v.w;
        }
        __syncthreads();
    }
#undef STAGE

    if (curbid >= 0) {
        float* dst = &g_sums[curbid * D + q * 4];
        atomicAdd(dst + 0, acc.x); atomicAdd(dst + 1, acc.y);
        atomicAdd(dst + 2, acc.z); atomicAdd(dst + 3, acc.w);
    }
}

// ---------------------------------------------------------------------------
// K3: C[g] = (sums[g]/cnt) @ W2^T + b
// ---------------------------------------------------------------------------
__global__ void k_ctx(const float* __restrict__ b) {
    __shared__ float sm[D];
    int g = blockIdx.x, t = threadIdx.x;
    int s = g_segstart[g], e = g_segstart[g + 1];
    int cnt = e - s;
    float inv = 1.f / (float)(cnt > 0 ? cnt : 1);
    sm[t] = g_sums[g * D + t] * inv;
    __syncthreads();
    float c = b[t];
#pragma unroll 8
    for (int k = 0; k < D; ++k) c += sm[k] * g_W2t[k * 128 + t];
    g_C[g * D + t] = c;
}

// ---------------------------------------------------------------------------
// K4: fp16x2 mma.sync GEMM. CTA 128x128, warp = 16 rows x 128 cols (R10
// shape). A tile staged via cp.async in two 32KB k-half groups into
// XOR-swizzled smem; B frags also cp.async. No prefetch registers.
// smem: [0,32K) B | [32K,64K) A-half0 | [64K,96K) A-half1. Epilogue reuses base.
// ---------------------------------------------------------------------------
#define STG_STRIDE 136
#define SMEM_BYTES 98304

__global__ void __launch_bounds__(256, 2)
k_gemm(const float* __restrict__ x, const int* __restrict__ bid,
       float* __restrict__ out, int N) {
    extern __shared__ __align__(16) uint32_t sh[];
    uint32_t* shB = sh;                      // 8192 u32 B frags
    char* shbase = (char*)sh;

    int tid = threadIdx.x;
    int w   = tid >> 5;
    int l   = tid & 31;
    int n0  = blockIdx.x * 128;
    bool full = (n0 + 128) <= N;

    uint32_t sB = smem_u32(sh);

    if (full) {
        const float4* xt = (const float4*)(x + (size_t)n0 * 128);
        // group 1: B frags + A half0
#pragma unroll
        for (int i = 0; i < 8; ++i)
            cp16(sB + (uint32_t)(i * 256 + tid) * 16, g_Bf + (i * 256 + tid) * 4);
#pragma unroll
        for (int i = 0; i < 8; ++i) {
            int qq = i * 256 + tid;
            int row = qq >> 4, o = qq & 15;
            uint32_t off = (uint32_t)(o * 16) ^ (uint32_t)((row & 3) << 6);
            cp16(sB + 32768u + (uint32_t)row * 256 + off, xt + row * 32 + o);
        }
        CP_COMMIT();
        // group 2: A half1
#pragma unroll
        for (int i = 0; i < 8; ++i) {
            int qq = i * 256 + tid;
            int row = qq >> 4, o = qq & 15;
            uint32_t off = (uint32_t)(o * 16) ^ (uint32_t)((row & 3) << 6);
            cp16(sB + 65536u + (uint32_t)row * 256 + off, xt + row * 32 + 16 + o);
        }
        CP_COMMIT();
    } else {
        // Tail CTA: guarded scalar staging of everything.
#pragma unroll
        for (int i = 0; i < 8; ++i) {
            int qq = i * 256 + tid;
            *(uint4*)(shB + qq * 4) = *(const uint4*)(g_Bf + qq * 4);
        }
        const float4 z4t = make_float4(0.f, 0.f, 0.f, 0.f);
#pragma unroll
        for (int i = 0; i < 16; ++i) {
            int qq = i * 256 + tid;               // 0..4095 over both halves
            int row = qq >> 5, o = qq & 31;       // o: float4 within full row
            int kh = o >> 4, oo = o & 15;
            float4 v = (n0 + row < N)
                ? *(const float4*)(x + (size_t)(n0 + row) * 128 + o * 4) : z4t;
            uint32_t off = (uint32_t)(oo * 16) ^ (uint32_t)((row & 3) << 6);
            *(float4*)(shbase + 32768 + kh * 32768 + row * 256 + off) = v;
        }
    }

    int g4 = l >> 2, c4 = l & 3;
    int row0 = w * 16 + g4;                      // local tile row

    float acc[16][4];
#pragma unroll
    for (int na = 0; na < 16; ++na)
#pragma unroll
        for (int j = 0; j < 4; ++j) acc[na][j] = 0.f;

#pragma unroll
    for (int kh = 0; kh < 2; ++kh) {
        if (full) {
            if (kh == 0) { CP_WAIT(1); } else { CP_WAIT(0); }
        }
        __syncthreads();
        const char* Ab = shbase + 32768 + kh * 32768;
        uint32_t aoff_sw = (uint32_t)((g4 & 3) << 6);

#pragma unroll
        for (int ksl = 0; ksl < 4; ++ksl) {
            uint32_t off = ((uint32_t)(ksl * 64 + c4 * 16)) ^ aoff_sw;
            float4 u = *(const float4*)(Ab + row0 * 256 + off);
            float4 v = *(const float4*)(Ab + (row0 + 8) * 256 + off);

            uint32_t ahi[4], alo[4];
            ahi[0] = pack_f16(u.x, u.y);
            ahi[1] = pack_f16(v.x, v.y);
            ahi[2] = pack_f16(u.z, u.w);
            ahi[3] = pack_f16(v.z, v.w);
            alo[0] = pack_f16(u.x - lo_h(ahi[0]), u.y - hi_h(ahi[0]));
            alo[1] = pack_f16(v.x - lo_h(ahi[1]), v.y - hi_h(ahi[1]));
            alo[2] = pack_f16(u.z - lo_h(ahi[2]), u.w - hi_h(ahi[2]));
            alo[3] = pack_f16(v.z - lo_h(ahi[3]), v.w - hi_h(ahi[3]));

            const uint32_t* bks = shB + (kh * 4 + ksl) * 16 * 64;
#pragma unroll
            for (int na = 0; na < 16; ++na) {
                uint2 bh = *(const uint2*)(bks + na * 64 + l * 2);
                uint32_t bhr[2] = {bh.x, bh.y};
                mma_f16(acc[na], ahi, bhr);
                mma_f16(acc[na], alo, bhr);
            }
        }
        __syncthreads();
    }

    // --- Epilogue: stage through smem (reuses B/A0 region), add C, store ---
    float* stg = (float*)sh;
    {
        int rl0 = w * 16 + g4;
#pragma unroll
        for (int na = 0; na < 16; ++na) {
            int cb = na * 8 + 2 * c4;
            *(float2*)(stg + rl0 * STG_STRIDE + cb) =
                make_float2(acc[na][0], acc[na][1]);
            *(float2*)(stg + (rl0 + 8) * STG_STRIDE + cb) =
                make_float2(acc[na][2], acc[na][3]);
        }
    }
    __syncthreads();
    {
        int cw = l * 4;
#pragma unroll
        for (int it = 0; it < 16; ++it) {
            int rloc = it * 8 + w;
            int n = n0 + rloc;
            if (n < N) {
                float4 v = *(float4*)(stg + rloc * STG_STRIDE + cw);
                int gidx = bid[n];
                float4 cv = *(const float4*)(g_C + (size_t)gidx * 128 + cw);
                v.x += cv.x; v.y += cv.y; v.z += cv.z; v.w += cv.w;
                *(float4*)(out + (size_t)n * 128 + cw) = v;
            }
        }
    }
}

// ---------------------------------------------------------------------------
extern "C" void kernel_launch(void* const* d_in, const int* in_sizes, int n_in,
                              void* d_out, int out_size) {
    const float* x   = (const float*)d_in[0];
    const int*   bid = (const int*)  d_in[1];
    const float* W   = (const float*)d_in[2];
    const float* b   = (const float*)d_in[3];
    float* out = (float*)d_out;
    int N = in_sizes[1];

    cudaFuncSetAttribute(k_gemm, cudaFuncAttributeMaxDynamicSharedMemorySize, SMEM_BYTES);

    k_prep<<<(N + 255) / 256, 256>>>(bid, N, W);
    k_sum<<<(N + 255) / 256, 256>>>(x, bid, N);
    k_ctx<<<G_NUM, 128>>>(b);
    k_gemm<<<(N + 127) / 128, 256, SMEM_BYTES>>>(x, bid, out, N);
}

// round 14
// speedup vs baseline: 1.1632x; 1.0770x over previous
#include <cuda_runtime.h>
#include <cuda_bf16.h>
#include <cuda_fp16.h>
#include <cstdint>

#define G_NUM 1024
#define D 128

// ---------------------------------------------------------------------------
// Device scratch
// ---------------------------------------------------------------------------
__device__ int   g_segstart[G_NUM + 1];
__device__ float g_sums[G_NUM * D];
__device__ float g_C[G_NUM * D];
__device__ float g_W2t[D * D];                 // W2 transposed: [k][t]
__device__ __align__(16) uint32_t g_Bf[8192];  // W1 fp16 B-fragments (col-permuted)

// ---------------------------------------------------------------------------
// Helpers
// ---------------------------------------------------------------------------
__device__ __forceinline__ uint32_t smem_u32(const void* p) {
    return (uint32_t)__cvta_generic_to_shared((void*)p);
}
__device__ __forceinline__ uint32_t pack_f16(float lo, float hi) {
    uint32_t r;
    asm("cvt.rn.f16x2.f32 %0, %1, %2;" : "=r"(r) : "f"(hi), "f"(lo));
    return r;
}
__device__ __forceinline__ void mma_f16(float* d, const uint32_t* a, const uint32_t* b) {
    asm volatile(
        "mma.sync.aligned.m16n8k16.row.col.f32.f16.f16.f32 "
        "{%0,%1,%2,%3}, {%4,%5,%6,%7}, {%8,%9}, {%0,%1,%2,%3};"
        : "+f"(d[0]), "+f"(d[1]), "+f"(d[2]), "+f"(d[3])
        : "r"(a[0]), "r"(a[1]), "r"(a[2]), "r"(a[3]), "r"(b[0]), "r"(b[1]));
}
__device__ __forceinline__ void cp16(uint32_t dst, const void* src) {
    asm volatile("cp.async.cg.shared.global [%0], [%1], 16;"
                 :: "r"(dst), "l"(src) : "memory");
}
#define CP_COMMIT() asm volatile("cp.async.commit_group;" ::: "memory")
#define CP_WAIT(n)  asm volatile("cp.async.wait_group %0;" :: "n"(n) : "memory")

// ---------------------------------------------------------------------------
// K1: zero sums + segment boundaries + W1 B-fragments + W2 transpose
// ---------------------------------------------------------------------------
__global__ void k_prep(const int* __restrict__ bid, int N, const float* __restrict__ W) {
    int i = blockIdx.x * blockDim.x + threadIdx.x;
    if (i < G_NUM * D) g_sums[i] = 0.f;
    if (i < N) {
        int b = bid[i];
        int prev = (i == 0) ? -1 : bid[i - 1];
        for (int g = prev + 1; g <= b; ++g) g_segstart[g] = i;
        if (i == N - 1)
            for (int g = b + 1; g <= G_NUM; ++g) g_segstart[g] = N;
    }
    if (i < 4096) {
        int ks = i >> 9;
        int na = (i >> 5) & 15;
        int l  = i & 31;
        int c  = l & 3;
        int n  = na * 8 + (l >> 2);
        int k0 = ks * 16 + 4 * c;
        const float* wr = W + (size_t)n * 256;
        g_Bf[i * 2 + 0] = pack_f16(wr[k0],     wr[k0 + 1]);
        g_Bf[i * 2 + 1] = pack_f16(wr[k0 + 2], wr[k0 + 3]);
    }
    if (i < D * D) {
        int k = i >> 7, t = i & 127;
        g_W2t[i] = W[(size_t)t * 256 + 128 + k];
    }
}

// ---------------------------------------------------------------------------
// K2: segment sums via cp.async double-buffered smem pipeline (R11 config)
// ---------------------------------------------------------------------------
__global__ void __launch_bounds__(256)
k_sum(const float* __restrict__ x, const int* __restrict__ bid, int N) {
    __shared__ __align__(16) float buf[2][32 * 128];
    __shared__ int sb[256];
    int tid = threadIdx.x;
    int n0 = blockIdx.x * 256;
    sb[tid] = (n0 + tid < N) ? bid[n0 + tid] : -1;
    __syncthreads();

    int h = tid >> 5;
    int q = tid & 31;
    const float4 z4 = make_float4(0.f, 0.f, 0.f, 0.f);
    float4 acc = z4;
    int curbid = sb[h];

    if (n0 + 256 > N) {
#pragma unroll 4
        for (int r = h; r < 256; r += 8) {
            int bv = sb[r];
            if (bv != curbid) {
                if (curbid >= 0) {
                    float* dst = &g_sums[curbid * D + q * 4];
                    atomicAdd(dst + 0, acc.x); atomicAdd(dst + 1, acc.y);
                    atomicAdd(dst + 2, acc.z); atomicAdd(dst + 3, acc.w);
                }
                acc = z4; curbid = bv;
            }
            if (bv >= 0) {
                float4 v = *(const float4*)(x + (size_t)(n0 + r) * D + q * 4);
                acc.x += v.x; acc.y += v.y; acc.z += v.z; acc.w += v.w;
            }
        }
        if (curbid >= 0) {
            float* dst = &g_sums[curbid * D + q * 4];
            atomicAdd(dst + 0, acc.x); atomicAdd(dst + 1, acc.y);
            atomicAdd(dst + 2, acc.z); atomicAdd(dst + 3, acc.w);
        }
        return;
    }

    const float4* src = (const float4*)(x + (size_t)n0 * 128);
    uint32_t sb0 = smem_u32(&buf[0][0]);
    uint32_t sb1 = smem_u32(&buf[1][0]);

#define STAGE(c, s)                                                            \
    do {                                                                       \
        uint32_t _d = ((s) ? sb1 : sb0) + (uint32_t)tid * 16;                  \
        const float4* _p = src + (c) * 1024 + tid;                             \
        cp16(_d + 0 * 4096, _p + 0 * 256);                                     \
        cp16(_d + 1 * 4096, _p + 1 * 256);                                     \
        cp16(_d + 2 * 4096, _p + 2 * 256);                                     \
        cp16(_d + 3 * 4096, _p + 3 * 256);                                     \
        CP_COMMIT();                                                           \
    } while (0)

    STAGE(0, 0);
#pragma unroll
    for (int c = 0; c < 8; ++c) {
        if (c < 7) {
            STAGE(c + 1, (c + 1) & 1);
            CP_WAIT(1);
        } else {
            CP_WAIT(0);
        }
        __syncthreads();
        const float* bp = buf[c & 1];
#pragma unroll
        for (int rr = 0; rr < 4; ++rr) {
            int r = rr * 8 + h;
            int bv = sb[c * 32 + r];
            float4 v = *(const float4*)(bp + r * 128 + q * 4);
            if (bv != curbid) {
                if (curbid >= 0) {
                    float* dst = &g_sums[curbid * D + q * 4];
                    atomicAdd(dst + 0, acc.x); atomicAdd(dst + 1, acc.y);
                    atomicAdd(dst + 2, acc.z); atomicAdd(dst + 3, acc.w);
                }
                acc = z4; curbid = bv;
            }
            acc.x += v.x; acc.y += v.y; acc.z += v.z; acc.w += v.w;
        }
        __syncthreads();
    }
#undef STAGE

    if (curbid >= 0) {
        float* dst = &g_sums[curbid * D + q * 4];
        atomicAdd(dst + 0, acc.x); atomicAdd(dst + 1, acc.y);
        atomicAdd(dst + 2, acc.z); atomicAdd(dst + 3, acc.w);
    }
}

// ---------------------------------------------------------------------------
// K3: C[g] = (sums[g]/cnt) @ W2^T + b
// ---------------------------------------------------------------------------
__global__ void k_ctx(const float* __restrict__ b) {
    __shared__ float sm[D];
    int g = blockIdx.x, t = threadIdx.x;
    int s = g_segstart[g], e = g_segstart[g + 1];
    int cnt = e - s;
    float inv = 1.f / (float)(cnt > 0 ? cnt : 1);
    sm[t] = g_sums[g * D + t] * inv;
    __syncthreads();
    float c = b[t];
#pragma unroll 8
    for (int k = 0; k < D; ++k) c += sm[k] * g_W2t[k * 128 + t];
    g_C[g * D + t] = c;
}

// ---------------------------------------------------------------------------
// K4: single-MMA fp16 GEMM (x and W both rounded to fp16; fp32 accum).
// R10 dataflow: CTA 128x128, warp = 16 rows x 128 cols, 2 CTA/SM,
// direct LDG with register prefetch distance 2.
// ---------------------------------------------------------------------------
#define STG_STRIDE 136
#define SMEM_BYTES (128 * STG_STRIDE * 4)

__global__ void __launch_bounds__(256, 2)
k_gemm(const float* __restrict__ x, const int* __restrict__ bid,
       float* __restrict__ out, int N) {
    extern __shared__ __align__(16) uint32_t sh[];
    uint32_t* shB = sh;

    int tid = threadIdx.x;
    int w   = tid >> 5;
    int l   = tid & 31;
    int n0  = blockIdx.x * 128;

#pragma unroll
    for (int i = 0; i < 8; ++i) {
        int q = i * 256 + tid;
        *(uint4*)(shB + q * 4) = *(const uint4*)(g_Bf + q * 4);
    }
    __syncthreads();

    int g4 = l >> 2, c4 = l & 3;
    int r0 = n0 + w * 16 + g4;
    int r1 = r0 + 8;
    const float* p0 = x + (size_t)r0 * 128;
    const float* p1 = x + (size_t)r1 * 128;
    bool full = (n0 + 128) <= N;
    bool vr0 = full || (r0 < N), vr1 = full || (r1 < N);
    const float4 z4 = make_float4(0.f, 0.f, 0.f, 0.f);

    float acc[16][4];
#pragma unroll
    for (int na = 0; na < 16; ++na)
#pragma unroll
        for (int j = 0; j < 4; ++j) acc[na][j] = 0.f;

    float4 cur[2][2], nxt[2][2];

#define LOAD_PAIR(dst, kp)                                                     \
    do {                                                                       \
        _Pragma("unroll")                                                      \
        for (int s_ = 0; s_ < 2; ++s_) {                                       \
            int k0_ = ((kp) * 2 + s_) * 16 + 4 * c4;                           \
            dst[s_][0] = vr0 ? *(const float4*)(p0 + k0_) : z4;                \
            dst[s_][1] = vr1 ? *(const float4*)(p1 + k0_) : z4;                \
        }                                                                      \
    } while (0)

    LOAD_PAIR(cur, 0);

#pragma unroll
    for (int kp = 0; kp < 4; ++kp) {
        if (kp < 3) LOAD_PAIR(nxt, kp + 1);

#pragma unroll
        for (int s = 0; s < 2; ++s) {
            int ks = kp * 2 + s;
            float4 u = cur[s][0];
            float4 v = cur[s][1];
            uint32_t a[4];
            a[0] = pack_f16(u.x, u.y);
            a[1] = pack_f16(v.x, v.y);
            a[2] = pack_f16(u.z, u.w);
            a[3] = pack_f16(v.z, v.w);

            const uint32_t* bks = shB + ks * 16 * 64;
#pragma unroll
            for (int na = 0; na < 16; ++na) {
                uint2 bh = *(const uint2*)(bks + na * 64 + l * 2);
                uint32_t bhr[2] = {bh.x, bh.y};
                mma_f16(acc[na], a, bhr);
            }
        }
#pragma unroll
        for (int s = 0; s < 2; ++s)
#pragma unroll
            for (int j = 0; j < 2; ++j) cur[s][j] = nxt[s][j];
    }
#undef LOAD_PAIR

    float* stg = (float*)sh;
    __syncthreads();
    {
        int rl0 = w * 16 + g4;
#pragma unroll
        for (int na = 0; na < 16; ++na) {
            int cb = na * 8 + 2 * c4;
            *(float2*)(stg + rl0 * STG_STRIDE + cb) =
                make_float2(acc[na][0], acc[na][1]);
            *(float2*)(stg + (rl0 + 8) * STG_STRIDE + cb) =
                make_float2(acc[na][2], acc[na][3]);
        }
    }
    __syncthreads();
    {
        int cw = l * 4;
#pragma unroll
        for (int it = 0; it < 16; ++it) {
            int rloc = it * 8 + w;
            int n = n0 + rloc;
            if (n < N) {
                float4 v = *(float4*)(stg + rloc * STG_STRIDE + cw);
                int gidx = bid[n];
                float4 cv = *(const float4*)(g_C + (size_t)gidx * 128 + cw);
                v.x += cv.x; v.y += cv.y; v.z += cv.z; v.w += cv.w;
                *(float4*)(out + (size_t)n * 128 + cw) = v;
            }
        }
    }
}

// ---------------------------------------------------------------------------
extern "C" void kernel_launch(void* const* d_in, const int* in_sizes, int n_in,
                              void* d_out, int out_size) {
    const float* x   = (const float*)d_in[0];
    const int*   bid = (const int*)  d_in[1];
    const float* W   = (const float*)d_in[2];
    const float* b   = (const float*)d_in[3];
    float* out = (float*)d_out;
    int N = in_sizes[1];

    cudaFuncSetAttribute(k_gemm, cudaFuncAttributeMaxDynamicSharedMemorySize, SMEM_BYTES);

    k_prep<<<(N + 255) / 256, 256>>>(bid, N, W);
    k_sum<<<(N + 255) / 256, 256>>>(x, bid, N);
    k_ctx<<<G_NUM, 128>>>(b);
    k_gemm<<<(N + 127) / 128, 256, SMEM_BYTES>>>(x, bid, out, N);
}